// round 14
// baseline (speedup 1.0000x reference)
#include <cuda_runtime.h>
#include <cstdint>

// ---------------- problem constants ----------------
#define B_      16
#define NF_     64
#define LAT_    512
#define IMG_    64
#define HW_     4096
#define NC_     4
#define CF_     9
#define FIN_    576          // NF * CF
#define FH_     64
#define FO_     64
#define FCH_    24
#define CAT_    2048         // LAT + NF*FCH
#define PDYN_   78016
#define KS_     16           // split-K factor for latent GEMMs

// dyn param offsets within one batch row
#define OFF_KIN   0
#define OFF_BIN   36864
#define OFF_KOUT  36928
#define OFF_BOUT  41024
#define OFF_KSK   41088
#define OFF_BSK   77952

// ---------------- scratch (device globals: allocation-free) ----------------
__device__ float g_outA [B_ * NF_ * HW_];       // ping-pong image state
__device__ float g_outB [B_ * NF_ * HW_];
__device__ float g_stats[B_ * 1152];            // mean[f*64+ch] @ +0, rstd @ +576 per b
__device__ float g_dynp [NC_ * B_ * PDYN_];     // all 4 iterations (20 MB)
__device__ float g_inj  [B_ * LAT_];
__device__ float g_inj4 [NC_ * B_ * LAT_];      // inj after 1..4 lin_res steps
__device__ float g_cat0 [B_ * CAT_];            // double-buffered cat
__device__ float g_cat1 [B_ * CAT_];
__device__ float g_partA[KS_ * B_ * CAT_];
__device__ float g_partB[KS_ * B_ * LAT_];
__device__ float g_partC[KS_ * B_ * LAT_];

// ---------------- helpers ----------------
__device__ __forceinline__ unsigned tf32_rna(float x) {
    unsigned u;
    asm("cvt.rna.tf32.f32 %0, %1;" : "=r"(u) : "f"(x));
    return u;
}
__device__ __forceinline__ float cvtf(float x) { return __uint_as_float(tf32_rna(x)); }

__device__ __forceinline__ void mma_tf32(float d[4], const unsigned a[4], const unsigned b[2]) {
    asm volatile(
        "mma.sync.aligned.m16n8k8.row.col.f32.tf32.tf32.f32 "
        "{%0,%1,%2,%3}, {%4,%5,%6,%7}, {%8,%9}, {%0,%1,%2,%3};\n"
        : "+f"(d[0]), "+f"(d[1]), "+f"(d[2]), "+f"(d[3])
        : "r"(a[0]), "r"(a[1]), "r"(a[2]), "r"(a[3]), "r"(b[0]), "r"(b[1]));
}

// ---------------- stem ----------------
__global__ void stem_kernel(const float* __restrict__ x, const float* __restrict__ w_in,
                            const float* __restrict__ b_in, float* __restrict__ out) {
    int bo = blockIdx.x;
    int b = bo >> 6, o = bo & 63;
    float w0 = w_in[o*3+0], w1 = w_in[o*3+1], w2 = w_in[o*3+2], bi = b_in[o];
    const float* xb = x + (size_t)b * 3 * HW_;
    float* op = out + (size_t)bo * HW_;
    for (int p = threadIdx.x; p < HW_; p += blockDim.x)
        op[p] = w0*xb[p] + w1*xb[HW_+p] + w2*xb[2*HW_+p] + bi;
}

// copy inj, zero BOTH cat buffers fully
__global__ void init_kernel(const float* __restrict__ inj_in, float* __restrict__ inj,
                            float* __restrict__ cat0, float* __restrict__ cat1) {
    int i = blockIdx.x * blockDim.x + threadIdx.x;
    if (i < B_ * CAT_) { cat0[i] = 0.0f; cat1[i] = 0.0f; }
    if (i < B_ * LAT_) inj[i] = inj_in[i];
}

// zero the freq region of one cat buffer
__global__ void zero_freq_kernel(float* __restrict__ cat) {
    int i = blockIdx.x * 256 + threadIdx.x;
    if (i < B_ * (CAT_ - LAT_)) {
        int b = i / (CAT_ - LAT_), j = i - b * (CAT_ - LAT_);
        cat[(size_t)b * CAT_ + LAT_ + j] = 0.0f;
    }
}

// ---------------- latent GEMMs ----------------
template<int FUSE>
__global__ void latk_gemm(const float* __restrict__ in, int in_stride,
                          const float* __restrict__ W, const float* __restrict__ bias,
                          float* __restrict__ out, int Din, int Dout) {
    extern __shared__ float ins[];
    const int Kslice = Din / gridDim.y;
    const int k0 = blockIdx.y * Kslice;
    const int j = blockIdx.x * 256 + threadIdx.x;

    for (int q = threadIdx.x; q < 16 * Kslice; q += 256) {
        int b = q / Kslice, k = q - b * Kslice;
        ins[q] = in[(size_t)b * in_stride + k0 + k];
    }
    __syncthreads();

    if (j >= Dout) return;

    float acc[16];
#pragma unroll
    for (int b = 0; b < 16; b++) acc[b] = 0.0f;

    const float* wp = W + (size_t)k0 * Dout + j;
    for (int k = 0; k < Kslice; k += 4) {
        float w0 = wp[(size_t)(k+0) * Dout];
        float w1 = wp[(size_t)(k+1) * Dout];
        float w2 = wp[(size_t)(k+2) * Dout];
        float w3 = wp[(size_t)(k+3) * Dout];
#pragma unroll
        for (int b = 0; b < 16; b++) {
            float a = acc[b];
            a = fmaf(w0, ins[b * Kslice + k + 0], a);
            a = fmaf(w1, ins[b * Kslice + k + 1], a);
            a = fmaf(w2, ins[b * Kslice + k + 2], a);
            a = fmaf(w3, ins[b * Kslice + k + 3], a);
            acc[b] = a;
        }
    }

    if (FUSE) {
        float bv = bias[j];
#pragma unroll
        for (int b = 0; b < 16; b++)
            out[(size_t)b * Dout + j] = acc[b] + bv;
    } else {
        float* pp = out + ((size_t)blockIdx.y * 16) * Dout + j;
#pragma unroll
        for (int b = 0; b < 16; b++)
            pp[(size_t)b * Dout] = acc[b];
    }
}

__global__ void latk_pair(const float* __restrict__ in, int in_stride,
                          const float* __restrict__ W1, int D1, float* __restrict__ partA,
                          const float* __restrict__ W2, int D2, float* __restrict__ partB,
                          int Din) {
    extern __shared__ float ins[];
    const int Kslice = Din / gridDim.y;
    const int k0 = blockIdx.y * Kslice;
    int j = blockIdx.x * 256 + threadIdx.x;

    for (int q = threadIdx.x; q < 16 * Kslice; q += 256) {
        int b = q / Kslice, k = q - b * Kslice;
        ins[q] = in[(size_t)b * in_stride + k0 + k];
    }
    __syncthreads();

    const float* W;
    float* part;
    int Dout;
    if (j < D1) { W = W1; part = partA; Dout = D1; }
    else        { W = W2; part = partB; Dout = D2; j -= D1; }

    float acc[16];
#pragma unroll
    for (int b = 0; b < 16; b++) acc[b] = 0.0f;

    const float* wp = W + (size_t)k0 * Dout + j;
    for (int k = 0; k < Kslice; k += 4) {
        float w0 = wp[(size_t)(k+0) * Dout];
        float w1 = wp[(size_t)(k+1) * Dout];
        float w2 = wp[(size_t)(k+2) * Dout];
        float w3 = wp[(size_t)(k+3) * Dout];
#pragma unroll
        for (int b = 0; b < 16; b++) {
            float a = acc[b];
            a = fmaf(w0, ins[b * Kslice + k + 0], a);
            a = fmaf(w1, ins[b * Kslice + k + 1], a);
            a = fmaf(w2, ins[b * Kslice + k + 2], a);
            a = fmaf(w3, ins[b * Kslice + k + 3], a);
            acc[b] = a;
        }
    }
    float* pp = part + ((size_t)blockIdx.y * 16) * Dout + j;
#pragma unroll
    for (int b = 0; b < 16; b++)
        pp[(size_t)b * Dout] = acc[b];
}

__global__ void latk_mid(const float* __restrict__ partA, const float* __restrict__ b1,
                         const float* __restrict__ W2, float* __restrict__ partC, int Din) {
    extern __shared__ float ins[];
    const int Kslice = Din / gridDim.y;
    const int k0 = blockIdx.y * Kslice;
    const int j = blockIdx.x * 256 + threadIdx.x;
    const int Dout = LAT_;

    for (int q = threadIdx.x; q < 16 * Kslice; q += 256) {
        int b = q / Kslice, k = k0 + (q - (q / Kslice) * Kslice);
        float s = b1[k];
#pragma unroll
        for (int ks = 0; ks < KS_; ks++)
            s += partA[((size_t)(ks * 16 + b)) * Din + k];
        ins[q] = (s > 0.0f) ? s : 0.2f * s;
    }
    __syncthreads();

    float acc[16];
#pragma unroll
    for (int b = 0; b < 16; b++) acc[b] = 0.0f;

    const float* wp = W2 + (size_t)k0 * Dout + j;
    for (int k = 0; k < Kslice; k += 4) {
        float w0 = wp[(size_t)(k+0) * Dout];
        float w1 = wp[(size_t)(k+1) * Dout];
        float w2 = wp[(size_t)(k+2) * Dout];
        float w3 = wp[(size_t)(k+3) * Dout];
#pragma unroll
        for (int b = 0; b < 16; b++) {
            float a = acc[b];
            a = fmaf(w0, ins[b * Kslice + k + 0], a);
            a = fmaf(w1, ins[b * Kslice + k + 1], a);
            a = fmaf(w2, ins[b * Kslice + k + 2], a);
            a = fmaf(w3, ins[b * Kslice + k + 3], a);
            acc[b] = a;
        }
    }
    float* pp = partC + ((size_t)blockIdx.y * 16) * Dout + j;
#pragma unroll
    for (int b = 0; b < 16; b++)
        pp[(size_t)b * Dout] = acc[b];
}

__global__ void reduce_final(const float* __restrict__ partC, const float* __restrict__ partB,
                             const float* __restrict__ b2, const float* __restrict__ bs,
                             float* __restrict__ out, int out_stride) {
    int i = blockIdx.x * 256 + threadIdx.x;
    if (i >= 16 * LAT_) return;
    int b = i >> 9, j = i & 511;
    float s = b2[j] + bs[j];
#pragma unroll
    for (int ks = 0; ks < KS_; ks++) {
        s += partC[((size_t)(ks * 16 + b)) * LAT_ + j];
        s += partB[((size_t)(ks * 16 + b)) * LAT_ + j];
    }
    out[(size_t)b * out_stride + j] = s;
}

__global__ void reduce_plain(const float* __restrict__ part, const float* __restrict__ bias,
                             float* __restrict__ out, int Dout) {
    int i = blockIdx.x * 256 + threadIdx.x;
    if (i >= 16 * Dout) return;
    int j = i % Dout;
    float s = bias[j];
#pragma unroll
    for (int ks = 0; ks < KS_; ks++)
        s += part[(size_t)ks * 16 * Dout + i];
    out[i] = s;
}

// ---------------- batched hypernetwork GEMM (tf32 MMA) ----------------
__global__ __launch_bounds__(256)
void dynp4_tc(const float* __restrict__ inj4, const float* __restrict__ W,
              const float* __restrict__ bias, float* __restrict__ dynp) {
    __shared__ __align__(16) float As[64][36];
    __shared__ __align__(16) float Bs[32][136];

    int n0 = blockIdx.x * 128;
    int tid = threadIdx.x;
    int wid = tid >> 5, lane = tid & 31;
    int gid = lane >> 2, tig = lane & 3;
    int warp_m = wid >> 2, warp_n = wid & 3;
    int m0w = warp_m * 32, n0w = warp_n * 32;

    float acc[2][4][4];
#pragma unroll
    for (int t = 0; t < 2; t++)
#pragma unroll
        for (int j = 0; j < 4; j++)
#pragma unroll
            for (int r = 0; r < 4; r++) acc[t][j][r] = 0.0f;

    for (int k0 = 0; k0 < LAT_; k0 += 32) {
        {
            int m = tid >> 2, kq = (tid & 3) * 8;
            float4 v0 = *(const float4*)&inj4[m * LAT_ + k0 + kq];
            float4 v1 = *(const float4*)&inj4[m * LAT_ + k0 + kq + 4];
            As[m][kq+0] = cvtf(v0.x); As[m][kq+1] = cvtf(v0.y);
            As[m][kq+2] = cvtf(v0.z); As[m][kq+3] = cvtf(v0.w);
            As[m][kq+4] = cvtf(v1.x); As[m][kq+5] = cvtf(v1.y);
            As[m][kq+6] = cvtf(v1.z); As[m][kq+7] = cvtf(v1.w);
        }
#pragma unroll
        for (int r = 0; r < 4; r++) {
            int s = tid + r * 256;
            int k = s >> 5, nq = (s & 31) * 4;
            float* Bsr = Bs[k] + nq;
            if (n0 + nq < PDYN_) {
                float4 v = *(const float4*)&W[(size_t)(k0 + k) * PDYN_ + n0 + nq];
                Bsr[0] = cvtf(v.x); Bsr[1] = cvtf(v.y);
                Bsr[2] = cvtf(v.z); Bsr[3] = cvtf(v.w);
            } else {
                Bsr[0] = 0.0f; Bsr[1] = 0.0f; Bsr[2] = 0.0f; Bsr[3] = 0.0f;
            }
        }
        __syncthreads();

#pragma unroll
        for (int ks = 0; ks < 32; ks += 8) {
            unsigned afr[2][4];
#pragma unroll
            for (int t = 0; t < 2; t++) {
                int mb = m0w + t * 16;
                afr[t][0] = __float_as_uint(As[mb + gid    ][ks + tig    ]);
                afr[t][1] = __float_as_uint(As[mb + gid + 8][ks + tig    ]);
                afr[t][2] = __float_as_uint(As[mb + gid    ][ks + tig + 4]);
                afr[t][3] = __float_as_uint(As[mb + gid + 8][ks + tig + 4]);
            }
#pragma unroll
            for (int j = 0; j < 4; j++) {
                int nb = n0w + j * 8;
                unsigned bfr[2];
                bfr[0] = __float_as_uint(Bs[ks + tig    ][nb + gid]);
                bfr[1] = __float_as_uint(Bs[ks + tig + 4][nb + gid]);
#pragma unroll
                for (int t = 0; t < 2; t++)
                    mma_tf32(acc[t][j], afr[t], bfr);
            }
        }
        __syncthreads();
    }

#pragma unroll
    for (int t = 0; t < 2; t++) {
        int m0 = m0w + t * 16 + gid;
        float* r0 = dynp + (size_t)m0 * PDYN_;
        float* r1 = dynp + (size_t)(m0 + 8) * PDYN_;
#pragma unroll
        for (int j = 0; j < 4; j++) {
            int n = n0 + n0w + j * 8 + 2 * tig;
            if (n < PDYN_) {
                float bv0 = bias[n], bv1 = bias[n + 1];
                r0[n]     = acc[t][j][0] + bv0;
                r0[n + 1] = acc[t][j][1] + bv1;
                r1[n]     = acc[t][j][2] + bv0;
                r1[n + 1] = acc[t][j][3] + bv1;
            }
        }
    }
}

// ---------------- stats: per-(b,ch) mean/rstd of the 9 perceive feature maps ----------------
__device__ __forceinline__ void reduce_stats(float vals[16], float* sh,
                                             float* __restrict__ mdst,
                                             float* __restrict__ rdst) {
    float s1 = 0.0f, s2 = 0.0f;
#pragma unroll
    for (int i = 0; i < 16; i++) { s1 += vals[i]; s2 += vals[i] * vals[i]; }
    __syncthreads();   // protect sh reuse across maps
    int lane = threadIdx.x & 31, w = threadIdx.x >> 5;
#pragma unroll
    for (int o = 16; o; o >>= 1) {
        s1 += __shfl_down_sync(0xffffffffu, s1, o);
        s2 += __shfl_down_sync(0xffffffffu, s2, o);
    }
    if (lane == 0) { sh[w] = s1; sh[8 + w] = s2; }
    __syncthreads();
    if (threadIdx.x == 0) {
        float a = 0.0f, c = 0.0f;
#pragma unroll
        for (int i = 0; i < 8; i++) { a += sh[i]; c += sh[8 + i]; }
        float m = a * (1.0f / 4096.0f);
        float v = c * (1.0f / 4096.0f) - m * m;
        *mdst = m;
        *rdst = rsqrtf(v + 1e-5f);
    }
}

__global__ void stats_kernel(const float* __restrict__ out, float* __restrict__ stats) {
    __shared__ float ch[HW_];
    __shared__ float sh[18];
    int bf = blockIdx.x;                 // b*64 + ch
    int b = bf >> 6, f = bf & 63;
    const float* src = out + (size_t)bf * HW_;
    for (int i = threadIdx.x; i < HW_; i += 256) ch[i] = src[i];
    __syncthreads();

    float* st = stats + (size_t)b * 1152;
    {
        float vals[16];
#pragma unroll
        for (int i = 0; i < 16; i++) vals[i] = ch[threadIdx.x + i * 256];
        reduce_stats(vals, sh, &st[0 * 64 + f], &st[576 + 0 * 64 + f]);
    }
    const int dils[4] = {1, 2, 4, 8};
#pragma unroll
    for (int di = 0; di < 4; di++) {
        int d = dils[di];
        float vsx[16], vsy[16];
#pragma unroll
        for (int i = 0; i < 16; i++) {
            int p = threadIdx.x + i * 256;
            int y = p >> 6, x = p & 63;
            int ym = y - d, yp = y + d, xm = x - d, xp = x + d;
            bool vym = ym >= 0, vyp = yp < 64, vxm = xm >= 0, vxp = xp < 64;
            float tl = (vym && vxm) ? ch[ym*64 + xm] : 0.0f;
            float tm = (vym)        ? ch[ym*64 + x ] : 0.0f;
            float tr = (vym && vxp) ? ch[ym*64 + xp] : 0.0f;
            float ml = (vxm)        ? ch[y *64 + xm] : 0.0f;
            float mr = (vxp)        ? ch[y *64 + xp] : 0.0f;
            float bl = (vyp && vxm) ? ch[yp*64 + xm] : 0.0f;
            float bm = (vyp)        ? ch[yp*64 + x ] : 0.0f;
            float br = (vyp && vxp) ? ch[yp*64 + xp] : 0.0f;
            vsx[i] = (tr - tl + 2.0f*(mr - ml) + br - bl) * 0.125f;
            vsy[i] = (bl + 2.0f*bm + br - tl - 2.0f*tm - tr) * 0.125f;
        }
        int msx = 1 + 2*di, msy = 2 + 2*di;
        reduce_stats(vsx, sh, &st[msx * 64 + f], &st[576 + msx * 64 + f]);
        reduce_stats(vsy, sh, &st[msy * 64 + f], &st[576 + msy * 64 + f]);
    }
}

// ---------------- fused perceive + dynamic conv + freq (tf32 tensor cores) ----------------
// smem layout (floats):
//   PE    @ 0      (24*132 = 3168)
//   STATS @ 3168   (1152)
//   union @ 4320:
//     phase1: As @+0 (128*36=4608), Bs @+4608 (32*136=4352), R @+8960 (32*384=12288)
//     phase2: H @+0 (64*136=8704), S @+8704 (8704), KO @+17408 (64*68=4352)
#define SM_PE   0
#define SM_ST   3168
#define SM_U    4320
#define SM_AS   (SM_U)
#define SM_BS   (SM_U + 4608)
#define SM_R    (SM_U + 8960)
#define SM_H    (SM_U)
#define SM_S    (SM_U + 8704)
#define SM_KO   (SM_U + 17408)
#define SM_TOT  (SM_U + 21760)   // 26080 floats = 104320 bytes

__global__ __launch_bounds__(256)
void dyna_fused_tc(const float* __restrict__ dynp, const float* __restrict__ img,
                   const float* __restrict__ stats, const float* __restrict__ pe,
                   float* __restrict__ out, float* __restrict__ cat) {
    extern __shared__ float sm[];

    int b = blockIdx.y;
    int n0 = blockIdx.x * 128;
    int r0row = n0 >> 6;                 // first image row of this 2-row tile
    const float* pb = dynp + (size_t)b * PDYN_;
    const float* ib = img + (size_t)b * NF_ * HW_;

    int tid = threadIdx.x;
    int wid = tid >> 5, lane = tid & 31;
    int gid = lane >> 2, tig = lane & 3;
    int warp_m = wid >> 1, warp_n = wid & 1;
    int m0w = warp_m * 32;
    int n0w = warp_n * 64;

    // stage pe tile + stats (persistent regions)
    for (int idx = tid; idx < 24 * 32; idx += 256) {
        int f = idx >> 5, q = (idx & 31) * 4;
        float4 v = *(const float4*)&pe[f * HW_ + n0 + q];
        float* d = sm + SM_PE + f * 132 + q;
        d[0] = v.x; d[1] = v.y; d[2] = v.z; d[3] = v.w;
    }
    for (int idx = tid; idx < 1152; idx += 256)
        sm[SM_ST + idx] = stats[(size_t)b * 1152 + idx];

    float acc[2][8][4];
#pragma unroll
    for (int t = 0; t < 2; t++)
#pragma unroll
        for (int j = 0; j < 8; j++)
#pragma unroll
            for (int r = 0; r < 4; r++) acc[t][j][r] = 0.0f;

    auto load_A = [&](int k0) {
#pragma unroll
        for (int r = 0; r < 4; r++) {
            int s = tid + r * 256;
            int m = s >> 3, kq = (s & 7) * 4;
            const float* arow = (m < 64) ? (pb + OFF_KIN + m * FIN_)
                                         : (pb + OFF_KSK + (m - 64) * FIN_);
            float4 v = *(const float4*)&arow[k0 + kq];
            float* As = sm + SM_AS + m * 36 + kq;
            As[0] = cvtf(v.x); As[1] = cvtf(v.y); As[2] = cvtf(v.z); As[3] = cvtf(v.w);
        }
    };
    auto mma_tile = [&]() {
#pragma unroll
        for (int ks = 0; ks < 32; ks += 8) {
            unsigned afr[2][4];
#pragma unroll
            for (int t = 0; t < 2; t++) {
                int mb = m0w + t * 16;
                afr[t][0] = __float_as_uint(sm[SM_AS + (mb + gid    ) * 36 + ks + tig    ]);
                afr[t][1] = __float_as_uint(sm[SM_AS + (mb + gid + 8) * 36 + ks + tig    ]);
                afr[t][2] = __float_as_uint(sm[SM_AS + (mb + gid    ) * 36 + ks + tig + 4]);
                afr[t][3] = __float_as_uint(sm[SM_AS + (mb + gid + 8) * 36 + ks + tig + 4]);
            }
            unsigned bfr[8][2];
#pragma unroll
            for (int j = 0; j < 8; j++) {
                int nb = n0w + j * 8;
                bfr[j][0] = __float_as_uint(sm[SM_BS + (ks + tig    ) * 136 + nb + gid]);
                bfr[j][1] = __float_as_uint(sm[SM_BS + (ks + tig + 4) * 136 + nb + gid]);
            }
#pragma unroll
            for (int t = 0; t < 2; t++)
#pragma unroll
                for (int j = 0; j < 8; j++)
                    mma_tf32(acc[t][j], afr[t], bfr[j]);
        }
    };
    // compute one 32-k sobel chunk from the staged R rows into Bs
    auto sobel_chunk = [&](int d, int c0, int f, bool isX) {
#pragma unroll
        for (int i = 0; i < 16; i++) {
            int s = tid + i * 256;
            int k = s >> 7, n = s & 127;
            int yl = n >> 6, x = n & 63;
            const float* Rb = sm + SM_R + k * 384 + yl * 64;
            bool vl = (x - d) >= 0, vr = (x + d) < 64;
            float tl = vl ? Rb[x - d]       : 0.0f;
            float tm =      Rb[x];
            float tr = vr ? Rb[x + d]       : 0.0f;
            float ml = vl ? Rb[128 + x - d] : 0.0f;
            float mr = vr ? Rb[128 + x + d] : 0.0f;
            float bl = vl ? Rb[256 + x - d] : 0.0f;
            float bm =      Rb[256 + x];
            float br = vr ? Rb[256 + x + d] : 0.0f;
            float v = isX ? (tr - tl + 2.0f*(mr - ml) + br - bl) * 0.125f
                          : (bl + 2.0f*bm + br - tl - 2.0f*tm - tr) * 0.125f;
            int ch = c0 + k;
            float mn = sm[SM_ST + f * 64 + ch];
            float rs = sm[SM_ST + 576 + f * 64 + ch];
            sm[SM_BS + k * 136 + n] = cvtf((v - mn) * rs);
        }
    };

    // ---- phase 1: identity chunks (feat 0) ----
    __syncthreads();    // PE/stats staged
#pragma unroll
    for (int h = 0; h < 2; h++) {
        load_A(h * 32);
#pragma unroll
        for (int i = 0; i < 16; i++) {
            int s = tid + i * 256;
            int k = s >> 7, n = s & 127;
            int ch = h * 32 + k;
            float v = ib[(size_t)ch * HW_ + n0 + n];
            float mn = sm[SM_ST + ch];
            float rs = sm[SM_ST + 576 + ch];
            sm[SM_BS + k * 136 + n] = cvtf((v - mn) * rs);
        }
        __syncthreads();
        mma_tile();
        __syncthreads();
    }

    // ---- phase 1: sobel chunks ----
    const int dils[4] = {1, 2, 4, 8};
#pragma unroll
    for (int di = 0; di < 4; di++) {
        int d = dils[di];
#pragma unroll
        for (int h = 0; h < 2; h++) {
            int c0 = h * 32;
            // stage R: 32 ch x 6 rows x 64 px
#pragma unroll
            for (int i = 0; i < 48; i++) {
                int s = tid + i * 256;
                int chl = s / 384;
                int rem = s - chl * 384;
                int slot = rem >> 6, x = rem & 63;
                int roff = (slot == 0) ? -d : (slot == 1) ? 1 - d : (slot == 2) ? 0
                         : (slot == 3) ? 1 : (slot == 4) ? d : 1 + d;
                int row = r0row + roff;
                float v = (row >= 0 && row < 64)
                          ? ib[(size_t)(c0 + chl) * HW_ + row * 64 + x] : 0.0f;
                sm[SM_R + chl * 384 + slot * 64 + x] = v;
            }
            load_A((1 + 2 * di) * 64 + c0);
            __syncthreads();                 // R + As ready
            sobel_chunk(d, c0, 1 + 2 * di, true);
            __syncthreads();                 // Bs(x) ready
            mma_tile();
            __syncthreads();                 // x-MMA done (As/Bs reusable; R intact)
            load_A((2 + 2 * di) * 64 + c0);
            sobel_chunk(d, c0, 2 + 2 * di, false);
            __syncthreads();                 // Bs(y) + As ready
            mma_tile();
            __syncthreads();                 // y-MMA done before next R overwrite
        }
    }

    // ---- phase 1 epilogue: h -> smem (tf32, leaky), s -> smem (fp32) ----
#pragma unroll
    for (int t = 0; t < 2; t++) {
#pragma unroll
        for (int half = 0; half < 2; half++) {
            int m = m0w + t * 16 + gid + half * 8;
#pragma unroll
            for (int j = 0; j < 8; j++) {
                int nl = n0w + j * 8 + 2 * tig;
                float v0 = acc[t][j][half * 2 + 0];
                float v1 = acc[t][j][half * 2 + 1];
                if (m < 64) {
                    float bv = pb[OFF_BIN + m];
                    v0 += bv; v1 += bv;
                    v0 = (v0 > 0.0f) ? v0 : 0.2f * v0;
                    v1 = (v1 > 0.0f) ? v1 : 0.2f * v1;
                    sm[SM_H + m * 136 + nl    ] = cvtf(v0);
                    sm[SM_H + m * 136 + nl + 1] = cvtf(v1);
                } else {
                    float bv = pb[OFF_BSK + (m - 64)];
                    sm[SM_S + (m - 64) * 136 + nl    ] = v0 + bv;
                    sm[SM_S + (m - 64) * 136 + nl + 1] = v1 + bv;
                }
            }
        }
    }
#pragma unroll
    for (int r = 0; r < 16; r++) {
        int idx = tid + r * 256;
        int o = idx >> 6, f = idx & 63;
        sm[SM_KO + o * 68 + f] = cvtf(pb[OFF_KOUT + o * 64 + f]);
    }
    __syncthreads();

    // ---- phase 2: out = s + k_out @ h ----
    int m02 = (wid >> 1) * 16;
    int n02 = (wid & 1) * 64;
    float c2[8][4];
#pragma unroll
    for (int j = 0; j < 8; j++) {
        int nl = n02 + j * 8 + 2 * tig;
        c2[j][0] = sm[SM_S + (m02 + gid    ) * 136 + nl    ];
        c2[j][1] = sm[SM_S + (m02 + gid    ) * 136 + nl + 1];
        c2[j][2] = sm[SM_S + (m02 + gid + 8) * 136 + nl    ];
        c2[j][3] = sm[SM_S + (m02 + gid + 8) * 136 + nl + 1];
    }
#pragma unroll
    for (int ks = 0; ks < 64; ks += 8) {
        unsigned a2[4];
        a2[0] = __float_as_uint(sm[SM_KO + (m02 + gid    ) * 68 + ks + tig    ]);
        a2[1] = __float_as_uint(sm[SM_KO + (m02 + gid + 8) * 68 + ks + tig    ]);
        a2[2] = __float_as_uint(sm[SM_KO + (m02 + gid    ) * 68 + ks + tig + 4]);
        a2[3] = __float_as_uint(sm[SM_KO + (m02 + gid + 8) * 68 + ks + tig + 4]);
#pragma unroll
        for (int j = 0; j < 8; j++) {
            int nb = n02 + j * 8;
            unsigned b2f[2];
            b2f[0] = __float_as_uint(sm[SM_H + (ks + tig    ) * 136 + nb + gid]);
            b2f[1] = __float_as_uint(sm[SM_H + (ks + tig + 4) * 136 + nb + gid]);
            mma_tf32(c2[j], a2, b2f);
        }
    }

    float bo0 = pb[OFF_BOUT + m02 + gid];
    float bo1 = pb[OFF_BOUT + m02 + gid + 8];
    float* ob = out + (size_t)b * FO_ * HW_;
#pragma unroll
    for (int j = 0; j < 8; j++) {
        int n = n0 + n02 + j * 8 + 2 * tig;
        float* r0 = ob + (size_t)(m02 + gid) * HW_;
        float* r1 = ob + (size_t)(m02 + gid + 8) * HW_;
        r0[n]     = c2[j][0] + bo0;
        r0[n + 1] = c2[j][1] + bo0;
        r1[n]     = c2[j][2] + bo1;
        r1[n + 1] = c2[j][3] + bo1;
    }

    // ---- fused freq ----
    float facc0[24], facc1[24];
#pragma unroll
    for (int f = 0; f < 24; f++) { facc0[f] = 0.0f; facc1[f] = 0.0f; }
#pragma unroll
    for (int j = 0; j < 8; j++) {
        int nl = n02 + j * 8 + 2 * tig;
        float v00 = c2[j][0] + bo0, v01 = c2[j][1] + bo0;
        float v10 = c2[j][2] + bo1, v11 = c2[j][3] + bo1;
#pragma unroll
        for (int f = 0; f < 24; f++) {
            float p0 = sm[SM_PE + f * 132 + nl];
            float p1 = sm[SM_PE + f * 132 + nl + 1];
            facc0[f] += v00 * p0 + v01 * p1;
            facc1[f] += v10 * p0 + v11 * p1;
        }
    }
    const float inv = 1.0f / 4096.0f;
    float* catb = cat + (size_t)b * CAT_ + LAT_;
    int mr0 = m02 + gid, mr1 = m02 + gid + 8;
#pragma unroll
    for (int f = 0; f < 24; f++) {
        float v0 = facc0[f];
        v0 += __shfl_xor_sync(0xffffffffu, v0, 1);
        v0 += __shfl_xor_sync(0xffffffffu, v0, 2);
        float v1 = facc1[f];
        v1 += __shfl_xor_sync(0xffffffffu, v1, 1);
        v1 += __shfl_xor_sync(0xffffffffu, v1, 2);
        if (tig == 0) {
            atomicAdd(&catb[mr0 * 24 + f], v0 * inv);
            atomicAdd(&catb[mr1 * 24 + f], v1 * inv);
        }
    }
}

// ---------------- host launcher ----------------
extern "C" void kernel_launch(void* const* d_in, const int* in_sizes, int n_in,
                              void* d_out, int out_size) {
    (void)in_sizes; (void)n_in; (void)out_size;
    const float* x      = (const float*)d_in[0];
    const float* inj_in = (const float*)d_in[1];
    const float* w_in   = (const float*)d_in[2];
    const float* b_in   = (const float*)d_in[3];
    const float* fl_w1  = (const float*)d_in[4];
    const float* fl_b1  = (const float*)d_in[5];
    const float* fl_w2  = (const float*)d_in[6];
    const float* fl_b2  = (const float*)d_in[7];
    const float* fl_ws  = (const float*)d_in[8];
    const float* fl_bs  = (const float*)d_in[9];
    const float* dyn_w  = (const float*)d_in[10];
    const float* dyn_b  = (const float*)d_in[11];
    const float* pe     = (const float*)d_in[12];
    const float* otl_w1 = (const float*)d_in[13];
    const float* otl_b1 = (const float*)d_in[14];
    const float* otl_w2 = (const float*)d_in[15];
    const float* otl_b2 = (const float*)d_in[16];
    const float* otl_ws = (const float*)d_in[17];
    const float* otl_bs = (const float*)d_in[18];
    const float* ltl_w  = (const float*)d_in[19];
    const float* ltl_b  = (const float*)d_in[20];

    float *p_outA, *p_outB, *p_stats, *p_dynp, *p_inj, *p_inj4, *p_cat0, *p_cat1;
    float *p_pA, *p_pB, *p_pC;
    cudaGetSymbolAddress((void**)&p_outA,  g_outA);
    cudaGetSymbolAddress((void**)&p_outB,  g_outB);
    cudaGetSymbolAddress((void**)&p_stats, g_stats);
    cudaGetSymbolAddress((void**)&p_dynp,  g_dynp);
    cudaGetSymbolAddress((void**)&p_inj,   g_inj);
    cudaGetSymbolAddress((void**)&p_inj4,  g_inj4);
    cudaGetSymbolAddress((void**)&p_cat0,  g_cat0);
    cudaGetSymbolAddress((void**)&p_cat1,  g_cat1);
    cudaGetSymbolAddress((void**)&p_pA,    g_partA);
    cudaGetSymbolAddress((void**)&p_pB,    g_partB);
    cudaGetSymbolAddress((void**)&p_pC,    g_partC);

    static cudaStream_t s1 = nullptr;
    static cudaEvent_t ev[9];
    static bool inited = false;
    if (!inited) {
        cudaFuncSetAttribute(dyna_fused_tc, cudaFuncAttributeMaxDynamicSharedMemorySize,
                             SM_TOT * 4);
        cudaStreamCreateWithFlags(&s1, cudaStreamNonBlocking);
        for (int i = 0; i < 9; i++)
            cudaEventCreateWithFlags(&ev[i], cudaEventDisableTiming);
        inited = true;
    }
    cudaStream_t s0 = 0;
    float* cat[2] = {p_cat0, p_cat1};
    float* img[2] = {p_outA, p_outB};

    // ---- s0: stem + init; fork s1 ----
    stem_kernel<<<B_ * NF_, 256, 0, s0>>>(x, w_in, b_in, p_outA);
    init_kernel<<<(B_ * CAT_ + 255) / 256, 256, 0, s0>>>(inj_in, p_inj, p_cat0, p_cat1);
    cudaEventRecord(ev[0], s0);
    cudaStreamWaitEvent(s1, ev[0], 0);

    // ---- s1: inj lin_res chain x4, then batched hypernetwork GEMM ----
    for (int c = 0; c < NC_; c++) {
        const float* src = (c == 0) ? p_inj : (p_inj4 + (size_t)(c - 1) * B_ * LAT_);
        latk_pair<<<dim3(4, KS_), 256, 16 * (LAT_ / KS_) * 4, s1>>>(
            src, LAT_, fl_w1, LAT_, p_pA, fl_ws, LAT_, p_pB, LAT_);
        latk_mid<<<dim3(2, KS_), 256, 16 * (LAT_ / KS_) * 4, s1>>>(p_pA, fl_b1, fl_w2, p_pC, LAT_);
        reduce_final<<<32, 256, 0, s1>>>(p_pC, p_pB, fl_b2, fl_bs,
                                         p_inj4 + (size_t)c * B_ * LAT_, LAT_);
    }
    dynp4_tc<<<(PDYN_ + 127) / 128, 256, 0, s1>>>(p_inj4, dyn_w, dyn_b, p_dynp);
    cudaEventRecord(ev[1], s1);   // dynp ready

    // ---- pipelined image loop: s0 = stats+dyna, s1 = otl chain ----
    for (int c = 0; c < NC_; c++) {
        float* catc = cat[c & 1];
        float* img_r = img[c & 1];
        float* img_w = img[(c + 1) & 1];
        stats_kernel<<<B_ * NF_, 256, 0, s0>>>(img_r, p_stats);
        if (c == 0) cudaStreamWaitEvent(s0, ev[1], 0);
        if (c >= 2) cudaStreamWaitEvent(s0, ev[6 + (c & 1)], 0);
        dyna_fused_tc<<<dim3(HW_ / 128, B_), 256, SM_TOT * 4, s0>>>(
            p_dynp + (size_t)c * B_ * PDYN_, img_r, p_stats, pe, img_w, catc);
        cudaEventRecord(ev[2 + c], s0);   // dyna(c) done

        // s1: otl chain for iter c (reads catc; writes other buffer's lat)
        cudaStreamWaitEvent(s1, ev[2 + c], 0);
        const float* w1c = otl_w1 + (size_t)c * CAT_ * CAT_;
        const float* b1c = otl_b1 + (size_t)c * CAT_;
        const float* w2c = otl_w2 + (size_t)c * CAT_ * LAT_;
        const float* b2c = otl_b2 + (size_t)c * LAT_;
        const float* wsc = otl_ws + (size_t)c * CAT_ * LAT_;
        const float* bsc = otl_bs + (size_t)c * LAT_;
        latk_pair<<<dim3(10, KS_), 256, 16 * (CAT_ / KS_) * 4, s1>>>(
            catc, CAT_, w1c, CAT_, p_pA, wsc, LAT_, p_pB, CAT_);
        if (c < 2) {
            zero_freq_kernel<<<(B_ * (CAT_ - LAT_) + 255) / 256, 256, 0, s1>>>(catc);
            cudaEventRecord(ev[6 + (c & 1)], s1);
        }
        latk_mid<<<dim3(2, KS_), 256, 16 * (CAT_ / KS_) * 4, s1>>>(p_pA, b1c, w2c, p_pC, CAT_);
        reduce_final<<<32, 256, 0, s1>>>(p_pC, p_pB, b2c, bsc, cat[(c + 1) & 1], CAT_);
    }

    // ---- s1: final projection (lat lives in cat[0] after reduce_final(3)) ----
    latk_gemm<0><<<dim3(2, KS_), 256, 16 * (LAT_ / KS_) * 4, s1>>>(
        p_cat0, CAT_, ltl_w, nullptr, p_pA, LAT_, LAT_);
    reduce_plain<<<32, 256, 0, s1>>>(p_pA, ltl_b, (float*)d_out, LAT_);

    // ---- join ----
    cudaEventRecord(ev[8], s1);
    cudaStreamWaitEvent(s0, ev[8], 0);
}

// round 15
// speedup vs baseline: 2.1809x; 2.1809x over previous
#include <cuda_runtime.h>
#include <cstdint>

// ---------------- problem constants ----------------
#define B_      16
#define NF_     64
#define LAT_    512
#define IMG_    64
#define HW_     4096
#define NC_     4
#define CF_     9
#define FIN_    576          // NF * CF
#define FH_     64
#define FO_     64
#define FCH_    24
#define CAT_    2048         // LAT + NF*FCH
#define PDYN_   78016
#define KSX_    32           // max split-K for latent GEMMs

// dyn param offsets within one batch row
#define OFF_KIN   0
#define OFF_BIN   36864
#define OFF_KOUT  36928
#define OFF_BOUT  41024
#define OFF_KSK   41088
#define OFF_BSK   77952

// ---------------- scratch (device globals: allocation-free) ----------------
__device__ float g_out  [B_ * NF_ * HW_];
__device__ float g_P    [B_ * FIN_ * HW_];
__device__ float g_dynp [NC_ * B_ * PDYN_];     // all 4 iterations (20 MB)
__device__ float g_inj  [B_ * LAT_];
__device__ float g_inj4 [NC_ * B_ * LAT_];      // inj after 1..4 lin_res steps
__device__ float g_cat0 [B_ * CAT_];            // double-buffered cat
__device__ float g_cat1 [B_ * CAT_];
__device__ float g_partA[KSX_ * B_ * CAT_];     // 4 MB
__device__ float g_partB[KSX_ * B_ * LAT_];
__device__ float g_partC[KSX_ * B_ * LAT_];

// ---------------- helpers ----------------
__device__ __forceinline__ unsigned tf32_rna(float x) {
    unsigned u;
    asm("cvt.rna.tf32.f32 %0, %1;" : "=r"(u) : "f"(x));
    return u;
}
__device__ __forceinline__ float cvtf(float x) { return __uint_as_float(tf32_rna(x)); }

__device__ __forceinline__ void mma_tf32(float d[4], const unsigned a[4], const unsigned b[2]) {
    asm volatile(
        "mma.sync.aligned.m16n8k8.row.col.f32.tf32.tf32.f32 "
        "{%0,%1,%2,%3}, {%4,%5,%6,%7}, {%8,%9}, {%0,%1,%2,%3};\n"
        : "+f"(d[0]), "+f"(d[1]), "+f"(d[2]), "+f"(d[3])
        : "r"(a[0]), "r"(a[1]), "r"(a[2]), "r"(a[3]), "r"(b[0]), "r"(b[1]));
}

// ---------------- stem ----------------
__global__ void stem_kernel(const float* __restrict__ x, const float* __restrict__ w_in,
                            const float* __restrict__ b_in, float* __restrict__ out) {
    int bo = blockIdx.x;
    int b = bo >> 6, o = bo & 63;
    float w0 = w_in[o*3+0], w1 = w_in[o*3+1], w2 = w_in[o*3+2], bi = b_in[o];
    const float* xb = x + (size_t)b * 3 * HW_;
    float* op = out + (size_t)bo * HW_;
    for (int p = threadIdx.x; p < HW_; p += blockDim.x)
        op[p] = w0*xb[p] + w1*xb[HW_+p] + w2*xb[2*HW_+p] + bi;
}

// copy inj, zero BOTH cat buffers fully
__global__ void init_kernel(const float* __restrict__ inj_in, float* __restrict__ inj,
                            float* __restrict__ cat0, float* __restrict__ cat1) {
    int i = blockIdx.x * blockDim.x + threadIdx.x;
    if (i < B_ * CAT_) { cat0[i] = 0.0f; cat1[i] = 0.0f; }
    if (i < B_ * LAT_) inj[i] = inj_in[i];
}

// zero the freq region of one cat buffer
__global__ void zero_freq_kernel(float* __restrict__ cat) {
    int i = blockIdx.x * 256 + threadIdx.x;
    if (i < B_ * (CAT_ - LAT_)) {
        int b = i / (CAT_ - LAT_), j = i - b * (CAT_ - LAT_);
        cat[(size_t)b * CAT_ + LAT_ + j] = 0.0f;
    }
}

// ---------------- latent GEMMs (split-K via gridDim.y) ----------------
template<int FUSE>
__global__ void latk_gemm(const float* __restrict__ in, int in_stride,
                          const float* __restrict__ W, const float* __restrict__ bias,
                          float* __restrict__ out, int Din, int Dout) {
    extern __shared__ float ins[];
    const int Kslice = Din / gridDim.y;
    const int k0 = blockIdx.y * Kslice;
    const int j = blockIdx.x * 256 + threadIdx.x;

    for (int q = threadIdx.x; q < 16 * Kslice; q += 256) {
        int b = q / Kslice, k = q - b * Kslice;
        ins[q] = in[(size_t)b * in_stride + k0 + k];
    }
    __syncthreads();

    if (j >= Dout) return;

    float acc[16];
#pragma unroll
    for (int b = 0; b < 16; b++) acc[b] = 0.0f;

    const float* wp = W + (size_t)k0 * Dout + j;
    for (int k = 0; k < Kslice; k += 4) {
        float w0 = wp[(size_t)(k+0) * Dout];
        float w1 = wp[(size_t)(k+1) * Dout];
        float w2 = wp[(size_t)(k+2) * Dout];
        float w3 = wp[(size_t)(k+3) * Dout];
#pragma unroll
        for (int b = 0; b < 16; b++) {
            float a = acc[b];
            a = fmaf(w0, ins[b * Kslice + k + 0], a);
            a = fmaf(w1, ins[b * Kslice + k + 1], a);
            a = fmaf(w2, ins[b * Kslice + k + 2], a);
            a = fmaf(w3, ins[b * Kslice + k + 3], a);
            acc[b] = a;
        }
    }

    if (FUSE) {
        float bv = bias[j];
#pragma unroll
        for (int b = 0; b < 16; b++)
            out[(size_t)b * Dout + j] = acc[b] + bv;
    } else {
        float* pp = out + ((size_t)blockIdx.y * 16) * Dout + j;
#pragma unroll
        for (int b = 0; b < 16; b++)
            pp[(size_t)b * Dout] = acc[b];
    }
}

__global__ void latk_pair(const float* __restrict__ in, int in_stride,
                          const float* __restrict__ W1, int D1, float* __restrict__ partA,
                          const float* __restrict__ W2, int D2, float* __restrict__ partB,
                          int Din) {
    extern __shared__ float ins[];
    const int Kslice = Din / gridDim.y;
    const int k0 = blockIdx.y * Kslice;
    int j = blockIdx.x * 256 + threadIdx.x;

    for (int q = threadIdx.x; q < 16 * Kslice; q += 256) {
        int b = q / Kslice, k = q - b * Kslice;
        ins[q] = in[(size_t)b * in_stride + k0 + k];
    }
    __syncthreads();

    const float* W;
    float* part;
    int Dout;
    if (j < D1) { W = W1; part = partA; Dout = D1; }
    else        { W = W2; part = partB; Dout = D2; j -= D1; }

    float acc[16];
#pragma unroll
    for (int b = 0; b < 16; b++) acc[b] = 0.0f;

    const float* wp = W + (size_t)k0 * Dout + j;
    for (int k = 0; k < Kslice; k += 4) {
        float w0 = wp[(size_t)(k+0) * Dout];
        float w1 = wp[(size_t)(k+1) * Dout];
        float w2 = wp[(size_t)(k+2) * Dout];
        float w3 = wp[(size_t)(k+3) * Dout];
#pragma unroll
        for (int b = 0; b < 16; b++) {
            float a = acc[b];
            a = fmaf(w0, ins[b * Kslice + k + 0], a);
            a = fmaf(w1, ins[b * Kslice + k + 1], a);
            a = fmaf(w2, ins[b * Kslice + k + 2], a);
            a = fmaf(w3, ins[b * Kslice + k + 3], a);
            acc[b] = a;
        }
    }
    float* pp = part + ((size_t)blockIdx.y * 16) * Dout + j;
#pragma unroll
    for (int b = 0; b < 16; b++)
        pp[(size_t)b * Dout] = acc[b];
}

// latk_mid: input = leaky(bias1 + sum_{nks} partA) reconstructed during staging; GEMM W2 -> partC.
__global__ void latk_mid(const float* __restrict__ partA, const float* __restrict__ b1,
                         const float* __restrict__ W2, float* __restrict__ partC,
                         int Din, int nks) {
    extern __shared__ float ins[];
    const int Kslice = Din / gridDim.y;
    const int k0 = blockIdx.y * Kslice;
    const int j = blockIdx.x * 256 + threadIdx.x;
    const int Dout = LAT_;

    for (int q = threadIdx.x; q < 16 * Kslice; q += 256) {
        int b = q / Kslice, k = k0 + (q - (q / Kslice) * Kslice);
        float s = b1[k];
        for (int ks = 0; ks < nks; ks++)
            s += partA[((size_t)(ks * 16 + b)) * Din + k];
        ins[q] = (s > 0.0f) ? s : 0.2f * s;
    }
    __syncthreads();

    float acc[16];
#pragma unroll
    for (int b = 0; b < 16; b++) acc[b] = 0.0f;

    const float* wp = W2 + (size_t)k0 * Dout + j;
    for (int k = 0; k < Kslice; k += 4) {
        float w0 = wp[(size_t)(k+0) * Dout];
        float w1 = wp[(size_t)(k+1) * Dout];
        float w2 = wp[(size_t)(k+2) * Dout];
        float w3 = wp[(size_t)(k+3) * Dout];
#pragma unroll
        for (int b = 0; b < 16; b++) {
            float a = acc[b];
            a = fmaf(w0, ins[b * Kslice + k + 0], a);
            a = fmaf(w1, ins[b * Kslice + k + 1], a);
            a = fmaf(w2, ins[b * Kslice + k + 2], a);
            a = fmaf(w3, ins[b * Kslice + k + 3], a);
            acc[b] = a;
        }
    }
    float* pp = partC + ((size_t)blockIdx.y * 16) * Dout + j;
#pragma unroll
    for (int b = 0; b < 16; b++)
        pp[(size_t)b * Dout] = acc[b];
}

__global__ void reduce_final(const float* __restrict__ partC, const float* __restrict__ partB,
                             const float* __restrict__ b2, const float* __restrict__ bs,
                             float* __restrict__ out, int out_stride, int nks) {
    int i = blockIdx.x * 256 + threadIdx.x;
    if (i >= 16 * LAT_) return;
    int b = i >> 9, j = i & 511;
    float s = b2[j] + bs[j];
    for (int ks = 0; ks < nks; ks++) {
        s += partC[((size_t)(ks * 16 + b)) * LAT_ + j];
        s += partB[((size_t)(ks * 16 + b)) * LAT_ + j];
    }
    out[(size_t)b * out_stride + j] = s;
}

__global__ void reduce_plain(const float* __restrict__ part, const float* __restrict__ bias,
                             float* __restrict__ out, int Dout, int nks) {
    int i = blockIdx.x * 256 + threadIdx.x;
    if (i >= 16 * Dout) return;
    int j = i % Dout;
    float s = bias[j];
    for (int ks = 0; ks < nks; ks++)
        s += part[(size_t)ks * 16 * Dout + i];
    out[i] = s;
}

// ---------------- batched hypernetwork GEMM (tf32 MMA) ----------------
__global__ __launch_bounds__(256)
void dynp4_tc(const float* __restrict__ inj4, const float* __restrict__ W,
              const float* __restrict__ bias, float* __restrict__ dynp) {
    __shared__ __align__(16) float As[64][36];
    __shared__ __align__(16) float Bs[32][136];

    int n0 = blockIdx.x * 128;
    int tid = threadIdx.x;
    int wid = tid >> 5, lane = tid & 31;
    int gid = lane >> 2, tig = lane & 3;
    int warp_m = wid >> 2, warp_n = wid & 3;
    int m0w = warp_m * 32, n0w = warp_n * 32;

    float acc[2][4][4];
#pragma unroll
    for (int t = 0; t < 2; t++)
#pragma unroll
        for (int j = 0; j < 4; j++)
#pragma unroll
            for (int r = 0; r < 4; r++) acc[t][j][r] = 0.0f;

    for (int k0 = 0; k0 < LAT_; k0 += 32) {
        {
            int m = tid >> 2, kq = (tid & 3) * 8;
            float4 v0 = *(const float4*)&inj4[m * LAT_ + k0 + kq];
            float4 v1 = *(const float4*)&inj4[m * LAT_ + k0 + kq + 4];
            As[m][kq+0] = cvtf(v0.x); As[m][kq+1] = cvtf(v0.y);
            As[m][kq+2] = cvtf(v0.z); As[m][kq+3] = cvtf(v0.w);
            As[m][kq+4] = cvtf(v1.x); As[m][kq+5] = cvtf(v1.y);
            As[m][kq+6] = cvtf(v1.z); As[m][kq+7] = cvtf(v1.w);
        }
#pragma unroll
        for (int r = 0; r < 4; r++) {
            int s = tid + r * 256;
            int k = s >> 5, nq = (s & 31) * 4;
            float* Bsr = Bs[k] + nq;
            if (n0 + nq < PDYN_) {
                float4 v = *(const float4*)&W[(size_t)(k0 + k) * PDYN_ + n0 + nq];
                Bsr[0] = cvtf(v.x); Bsr[1] = cvtf(v.y);
                Bsr[2] = cvtf(v.z); Bsr[3] = cvtf(v.w);
            } else {
                Bsr[0] = 0.0f; Bsr[1] = 0.0f; Bsr[2] = 0.0f; Bsr[3] = 0.0f;
            }
        }
        __syncthreads();

#pragma unroll
        for (int ks = 0; ks < 32; ks += 8) {
            unsigned afr[2][4];
#pragma unroll
            for (int t = 0; t < 2; t++) {
                int mb = m0w + t * 16;
                afr[t][0] = __float_as_uint(As[mb + gid    ][ks + tig    ]);
                afr[t][1] = __float_as_uint(As[mb + gid + 8][ks + tig    ]);
                afr[t][2] = __float_as_uint(As[mb + gid    ][ks + tig + 4]);
                afr[t][3] = __float_as_uint(As[mb + gid + 8][ks + tig + 4]);
            }
#pragma unroll
            for (int j = 0; j < 4; j++) {
                int nb = n0w + j * 8;
                unsigned bfr[2];
                bfr[0] = __float_as_uint(Bs[ks + tig    ][nb + gid]);
                bfr[1] = __float_as_uint(Bs[ks + tig + 4][nb + gid]);
#pragma unroll
                for (int t = 0; t < 2; t++)
                    mma_tf32(acc[t][j], afr[t], bfr);
            }
        }
        __syncthreads();
    }

#pragma unroll
    for (int t = 0; t < 2; t++) {
        int m0 = m0w + t * 16 + gid;
        float* r0 = dynp + (size_t)m0 * PDYN_;
        float* r1 = dynp + (size_t)(m0 + 8) * PDYN_;
#pragma unroll
        for (int j = 0; j < 4; j++) {
            int n = n0 + n0w + j * 8 + 2 * tig;
            if (n < PDYN_) {
                float bv0 = bias[n], bv1 = bias[n + 1];
                r0[n]     = acc[t][j][0] + bv0;
                r0[n + 1] = acc[t][j][1] + bv1;
                r1[n]     = acc[t][j][2] + bv0;
                r1[n + 1] = acc[t][j][3] + bv1;
            }
        }
    }
}

// ---------------- perceive (9 depthwise sobel feats) + instance norm ----------------
__device__ __forceinline__ void reduce_write_map(float vals[16], float* __restrict__ dst,
                                                 float* sh) {
    float s1 = 0.0f, s2 = 0.0f;
#pragma unroll
    for (int i = 0; i < 16; i++) { s1 += vals[i]; s2 += vals[i] * vals[i]; }
    __syncthreads();
    int lane = threadIdx.x & 31, w = threadIdx.x >> 5;
#pragma unroll
    for (int o = 16; o; o >>= 1) {
        s1 += __shfl_down_sync(0xffffffffu, s1, o);
        s2 += __shfl_down_sync(0xffffffffu, s2, o);
    }
    if (lane == 0) { sh[w] = s1; sh[8 + w] = s2; }
    __syncthreads();
    if (threadIdx.x == 0) {
        float a = 0.0f, c = 0.0f;
#pragma unroll
        for (int i = 0; i < 8; i++) { a += sh[i]; c += sh[8 + i]; }
        float m = a * (1.0f / 4096.0f);
        float v = c * (1.0f / 4096.0f) - m * m;
        sh[16] = m;
        sh[17] = rsqrtf(v + 1e-5f);
    }
    __syncthreads();
    float mean = sh[16], rstd = sh[17];
#pragma unroll
    for (int i = 0; i < 16; i++)
        dst[threadIdx.x + i * 256] = (vals[i] - mean) * rstd;
}

__global__ void perceive_inorm_kernel(const float* __restrict__ out, float* __restrict__ P) {
    __shared__ float ch[HW_];
    __shared__ float sh[18];
    int bf = blockIdx.x;
    int b = bf >> 6, f = bf & 63;
    const float* src = out + (size_t)bf * HW_;
    for (int i = threadIdx.x; i < HW_; i += 256) ch[i] = src[i];
    __syncthreads();

    float* Pb = P + (size_t)b * FIN_ * HW_;
    {
        float vals[16];
#pragma unroll
        for (int i = 0; i < 16; i++) vals[i] = ch[threadIdx.x + i * 256];
        reduce_write_map(vals, Pb + (size_t)(0 * NF_ + f) * HW_, sh);
    }
    const int dils[4] = {1, 2, 4, 8};
#pragma unroll
    for (int di = 0; di < 4; di++) {
        int d = dils[di];
        float vsx[16], vsy[16];
#pragma unroll
        for (int i = 0; i < 16; i++) {
            int p = threadIdx.x + i * 256;
            int y = p >> 6, x = p & 63;
            int ym = y - d, yp = y + d, xm = x - d, xp = x + d;
            bool vym = ym >= 0, vyp = yp < 64, vxm = xm >= 0, vxp = xp < 64;
            float tl = (vym && vxm) ? ch[ym*64 + xm] : 0.0f;
            float tm = (vym)        ? ch[ym*64 + x ] : 0.0f;
            float tr = (vym && vxp) ? ch[ym*64 + xp] : 0.0f;
            float ml = (vxm)        ? ch[y *64 + xm] : 0.0f;
            float mr = (vxp)        ? ch[y *64 + xp] : 0.0f;
            float bl = (vyp && vxm) ? ch[yp*64 + xm] : 0.0f;
            float bm = (vyp)        ? ch[yp*64 + x ] : 0.0f;
            float br = (vyp && vxp) ? ch[yp*64 + xp] : 0.0f;
            vsx[i] = (tr - tl + 2.0f*(mr - ml) + br - bl) * 0.125f;
            vsy[i] = (bl + 2.0f*bm + br - tl - 2.0f*tm - tr) * 0.125f;
        }
        int msx = 1 + 2*di, msy = 2 + 2*di;
        reduce_write_map(vsx, Pb + (size_t)(msx * NF_ + f) * HW_, sh);
        reduce_write_map(vsy, Pb + (size_t)(msy * NF_ + f) * HW_, sh);
    }
}

// ---------------- fused dynamic conv + freq (tf32 tensor cores) ----------------
#define SMB_AS0 0
#define SMB_BS0 4608
#define SMB_AS1 8960
#define SMB_BS1 13568
#define SM_H    0
#define SM_S    8704
#define SM_KO   17408
#define SM_PE   21760
#define SM_TOT  24928        // floats (99712 bytes)

__global__ __launch_bounds__(256)
void dyna_fused_tc(const float* __restrict__ dynp, const float* __restrict__ P,
                   const float* __restrict__ pe, float* __restrict__ out,
                   float* __restrict__ cat) {
    extern __shared__ float sm[];

    int b = blockIdx.y;
    int n0 = blockIdx.x * 128;
    const float* pb = dynp + (size_t)b * PDYN_;
    const float* Bm = P + (size_t)b * FIN_ * HW_;

    int tid = threadIdx.x;
    int wid = tid >> 5, lane = tid & 31;
    int gid = lane >> 2, tig = lane & 3;
    int warp_m = wid >> 1, warp_n = wid & 1;
    int m0w = warp_m * 32;
    int n0w = warp_n * 64;

    for (int idx = tid; idx < 24 * 32; idx += 256) {
        int f = idx >> 5, q = (idx & 31) * 4;
        float4 v = *(const float4*)&pe[f * HW_ + n0 + q];
        float* d = sm + SM_PE + f * 132 + q;
        d[0] = v.x; d[1] = v.y; d[2] = v.z; d[3] = v.w;
    }

    float acc[2][8][4];
#pragma unroll
    for (int t = 0; t < 2; t++)
#pragma unroll
        for (int j = 0; j < 8; j++)
#pragma unroll
            for (int r = 0; r < 4; r++) acc[t][j][r] = 0.0f;

    float4 ra[4], rb[4];
    auto load_tile = [&](int k0) {
#pragma unroll
        for (int r = 0; r < 4; r++) {
            int s = tid + r * 256;
            int m = s >> 3, kq = (s & 7) * 4;
            const float* arow = (m < 64) ? (pb + OFF_KIN + m * FIN_)
                                         : (pb + OFF_KSK + (m - 64) * FIN_);
            ra[r] = *(const float4*)&arow[k0 + kq];
        }
#pragma unroll
        for (int r = 0; r < 4; r++) {
            int s = tid + r * 256;
            int k = s >> 5, nq = (s & 31) * 4;
            rb[r] = *(const float4*)&Bm[(size_t)(k0 + k) * HW_ + n0 + nq];
        }
    };
    auto store_tile = [&](int asB, int bsB) {
#pragma unroll
        for (int r = 0; r < 4; r++) {
            int s = tid + r * 256;
            int m = s >> 3, kq = (s & 7) * 4;
            float* As = sm + asB + m * 36 + kq;
            As[0] = cvtf(ra[r].x); As[1] = cvtf(ra[r].y);
            As[2] = cvtf(ra[r].z); As[3] = cvtf(ra[r].w);
        }
#pragma unroll
        for (int r = 0; r < 4; r++) {
            int s = tid + r * 256;
            int k = s >> 5, nq = (s & 31) * 4;
            float* Bs = sm + bsB + k * 136 + nq;
            Bs[0] = cvtf(rb[r].x); Bs[1] = cvtf(rb[r].y);
            Bs[2] = cvtf(rb[r].z); Bs[3] = cvtf(rb[r].w);
        }
    };
    auto mma_tile = [&](int asB, int bsB) {
#pragma unroll
        for (int ks = 0; ks < 32; ks += 8) {
            unsigned afr[2][4];
#pragma unroll
            for (int t = 0; t < 2; t++) {
                int mb = m0w + t * 16;
                afr[t][0] = __float_as_uint(sm[asB + (mb + gid    ) * 36 + ks + tig    ]);
                afr[t][1] = __float_as_uint(sm[asB + (mb + gid + 8) * 36 + ks + tig    ]);
                afr[t][2] = __float_as_uint(sm[asB + (mb + gid    ) * 36 + ks + tig + 4]);
                afr[t][3] = __float_as_uint(sm[asB + (mb + gid + 8) * 36 + ks + tig + 4]);
            }
            unsigned bfr[8][2];
#pragma unroll
            for (int j = 0; j < 8; j++) {
                int nb = n0w + j * 8;
                bfr[j][0] = __float_as_uint(sm[bsB + (ks + tig    ) * 136 + nb + gid]);
                bfr[j][1] = __float_as_uint(sm[bsB + (ks + tig + 4) * 136 + nb + gid]);
            }
#pragma unroll
            for (int t = 0; t < 2; t++)
#pragma unroll
                for (int j = 0; j < 8; j++)
                    mma_tf32(acc[t][j], afr[t], bfr[j]);
        }
    };

    load_tile(0);
    store_tile(SMB_AS0, SMB_BS0);
    __syncthreads();
    for (int t = 0; t < 18; t += 2) {
        load_tile((t + 1) * 32);
        mma_tile(SMB_AS0, SMB_BS0);
        store_tile(SMB_AS1, SMB_BS1);
        __syncthreads();
        if (t + 2 < 18) load_tile((t + 2) * 32);
        mma_tile(SMB_AS1, SMB_BS1);
        if (t + 2 < 18) store_tile(SMB_AS0, SMB_BS0);
        __syncthreads();
    }

#pragma unroll
    for (int t = 0; t < 2; t++) {
#pragma unroll
        for (int half = 0; half < 2; half++) {
            int m = m0w + t * 16 + gid + half * 8;
#pragma unroll
            for (int j = 0; j < 8; j++) {
                int nl = n0w + j * 8 + 2 * tig;
                float v0 = acc[t][j][half * 2 + 0];
                float v1 = acc[t][j][half * 2 + 1];
                if (m < 64) {
                    float bv = pb[OFF_BIN + m];
                    v0 += bv; v1 += bv;
                    v0 = (v0 > 0.0f) ? v0 : 0.2f * v0;
                    v1 = (v1 > 0.0f) ? v1 : 0.2f * v1;
                    sm[SM_H + m * 136 + nl    ] = cvtf(v0);
                    sm[SM_H + m * 136 + nl + 1] = cvtf(v1);
                } else {
                    float bv = pb[OFF_BSK + (m - 64)];
                    sm[SM_S + (m - 64) * 136 + nl    ] = v0 + bv;
                    sm[SM_S + (m - 64) * 136 + nl + 1] = v1 + bv;
                }
            }
        }
    }
#pragma unroll
    for (int r = 0; r < 16; r++) {
        int idx = tid + r * 256;
        int o = idx >> 6, f = idx & 63;
        sm[SM_KO + o * 68 + f] = cvtf(pb[OFF_KOUT + o * 64 + f]);
    }
    __syncthreads();

    int m02 = (wid >> 1) * 16;
    int n02 = (wid & 1) * 64;
    float c2[8][4];
#pragma unroll
    for (int j = 0; j < 8; j++) {
        int nl = n02 + j * 8 + 2 * tig;
        c2[j][0] = sm[SM_S + (m02 + gid    ) * 136 + nl    ];
        c2[j][1] = sm[SM_S + (m02 + gid    ) * 136 + nl + 1];
        c2[j][2] = sm[SM_S + (m02 + gid + 8) * 136 + nl    ];
        c2[j][3] = sm[SM_S + (m02 + gid + 8) * 136 + nl + 1];
    }
#pragma unroll
    for (int ks = 0; ks < 64; ks += 8) {
        unsigned a2[4];
        a2[0] = __float_as_uint(sm[SM_KO + (m02 + gid    ) * 68 + ks + tig    ]);
        a2[1] = __float_as_uint(sm[SM_KO + (m02 + gid + 8) * 68 + ks + tig    ]);
        a2[2] = __float_as_uint(sm[SM_KO + (m02 + gid    ) * 68 + ks + tig + 4]);
        a2[3] = __float_as_uint(sm[SM_KO + (m02 + gid + 8) * 68 + ks + tig + 4]);
#pragma unroll
        for (int j = 0; j < 8; j++) {
            int nb = n02 + j * 8;
            unsigned b2f[2];
            b2f[0] = __float_as_uint(sm[SM_H + (ks + tig    ) * 136 + nb + gid]);
            b2f[1] = __float_as_uint(sm[SM_H + (ks + tig + 4) * 136 + nb + gid]);
            mma_tf32(c2[j], a2, b2f);
        }
    }

    float bo0 = pb[OFF_BOUT + m02 + gid];
    float bo1 = pb[OFF_BOUT + m02 + gid + 8];
    float* ob = out + (size_t)b * FO_ * HW_;
#pragma unroll
    for (int j = 0; j < 8; j++) {
        int n = n0 + n02 + j * 8 + 2 * tig;
        float* r0 = ob + (size_t)(m02 + gid) * HW_;
        float* r1 = ob + (size_t)(m02 + gid + 8) * HW_;
        r0[n]     = c2[j][0] + bo0;
        r0[n + 1] = c2[j][1] + bo0;
        r1[n]     = c2[j][2] + bo1;
        r1[n + 1] = c2[j][3] + bo1;
    }

    float facc0[24], facc1[24];
#pragma unroll
    for (int f = 0; f < 24; f++) { facc0[f] = 0.0f; facc1[f] = 0.0f; }
#pragma unroll
    for (int j = 0; j < 8; j++) {
        int nl = n02 + j * 8 + 2 * tig;
        float v00 = c2[j][0] + bo0, v01 = c2[j][1] + bo0;
        float v10 = c2[j][2] + bo1, v11 = c2[j][3] + bo1;
#pragma unroll
        for (int f = 0; f < 24; f++) {
            float p0 = sm[SM_PE + f * 132 + nl];
            float p1 = sm[SM_PE + f * 132 + nl + 1];
            facc0[f] += v00 * p0 + v01 * p1;
            facc1[f] += v10 * p0 + v11 * p1;
        }
    }
    const float inv = 1.0f / 4096.0f;
    float* catb = cat + (size_t)b * CAT_ + LAT_;
    int mr0 = m02 + gid, mr1 = m02 + gid + 8;
#pragma unroll
    for (int f = 0; f < 24; f++) {
        float v0 = facc0[f];
        v0 += __shfl_xor_sync(0xffffffffu, v0, 1);
        v0 += __shfl_xor_sync(0xffffffffu, v0, 2);
        float v1 = facc1[f];
        v1 += __shfl_xor_sync(0xffffffffu, v1, 1);
        v1 += __shfl_xor_sync(0xffffffffu, v1, 2);
        if (tig == 0) {
            atomicAdd(&catb[mr0 * 24 + f], v0 * inv);
            atomicAdd(&catb[mr1 * 24 + f], v1 * inv);
        }
    }
}

// ---------------- host launcher ----------------
extern "C" void kernel_launch(void* const* d_in, const int* in_sizes, int n_in,
                              void* d_out, int out_size) {
    (void)in_sizes; (void)n_in; (void)out_size;
    const float* x      = (const float*)d_in[0];
    const float* inj_in = (const float*)d_in[1];
    const float* w_in   = (const float*)d_in[2];
    const float* b_in   = (const float*)d_in[3];
    const float* fl_w1  = (const float*)d_in[4];
    const float* fl_b1  = (const float*)d_in[5];
    const float* fl_w2  = (const float*)d_in[6];
    const float* fl_b2  = (const float*)d_in[7];
    const float* fl_ws  = (const float*)d_in[8];
    const float* fl_bs  = (const float*)d_in[9];
    const float* dyn_w  = (const float*)d_in[10];
    const float* dyn_b  = (const float*)d_in[11];
    const float* pe     = (const float*)d_in[12];
    const float* otl_w1 = (const float*)d_in[13];
    const float* otl_b1 = (const float*)d_in[14];
    const float* otl_w2 = (const float*)d_in[15];
    const float* otl_b2 = (const float*)d_in[16];
    const float* otl_ws = (const float*)d_in[17];
    const float* otl_bs = (const float*)d_in[18];
    const float* ltl_w  = (const float*)d_in[19];
    const float* ltl_b  = (const float*)d_in[20];

    float *p_out, *p_P, *p_dynp, *p_inj, *p_inj4, *p_cat0, *p_cat1, *p_pA, *p_pB, *p_pC;
    cudaGetSymbolAddress((void**)&p_out,  g_out);
    cudaGetSymbolAddress((void**)&p_P,    g_P);
    cudaGetSymbolAddress((void**)&p_dynp, g_dynp);
    cudaGetSymbolAddress((void**)&p_inj,  g_inj);
    cudaGetSymbolAddress((void**)&p_inj4, g_inj4);
    cudaGetSymbolAddress((void**)&p_cat0, g_cat0);
    cudaGetSymbolAddress((void**)&p_cat1, g_cat1);
    cudaGetSymbolAddress((void**)&p_pA,   g_partA);
    cudaGetSymbolAddress((void**)&p_pB,   g_partB);
    cudaGetSymbolAddress((void**)&p_pC,   g_partC);

    static cudaStream_t s1 = nullptr;
    static cudaEvent_t ev[9];
    static bool inited = false;
    if (!inited) {
        cudaFuncSetAttribute(dyna_fused_tc, cudaFuncAttributeMaxDynamicSharedMemorySize,
                             SM_TOT * 4);
        cudaStreamCreateWithFlags(&s1, cudaStreamNonBlocking);
        for (int i = 0; i < 9; i++)
            cudaEventCreateWithFlags(&ev[i], cudaEventDisableTiming);
        inited = true;
    }
    cudaStream_t s0 = 0;
    float* cat[2] = {p_cat0, p_cat1};

    // ---- s0: init FIRST (fork point), then stem ----
    init_kernel<<<(B_ * CAT_ + 255) / 256, 256, 0, s0>>>(inj_in, p_inj, p_cat0, p_cat1);
    cudaEventRecord(ev[0], s0);
    stem_kernel<<<B_ * NF_, 256, 0, s0>>>(x, w_in, b_in, p_out);
    cudaStreamWaitEvent(s1, ev[0], 0);

    // ---- s1: inj lin_res chain x4 (split-K 32), then batched hypernetwork GEMM ----
    for (int c = 0; c < NC_; c++) {
        const float* src = (c == 0) ? p_inj : (p_inj4 + (size_t)(c - 1) * B_ * LAT_);
        latk_pair<<<dim3(4, 32), 256, 16 * (LAT_ / 32) * 4, s1>>>(
            src, LAT_, fl_w1, LAT_, p_pA, fl_ws, LAT_, p_pB, LAT_);
        latk_mid<<<dim3(2, 32), 256, 16 * (LAT_ / 32) * 4, s1>>>(
            p_pA, fl_b1, fl_w2, p_pC, LAT_, 32);
        reduce_final<<<32, 256, 0, s1>>>(p_pC, p_pB, fl_b2, fl_bs,
                                         p_inj4 + (size_t)c * B_ * LAT_, LAT_, 32);
    }
    dynp4_tc<<<(PDYN_ + 127) / 128, 256, 0, s1>>>(p_inj4, dyn_w, dyn_b, p_dynp);
    cudaEventRecord(ev[1], s1);   // dynp ready

    // ---- pipelined image loop: s0 = perceive+dyna, s1 = otl chain ----
    for (int c = 0; c < NC_; c++) {
        float* catc = cat[c & 1];
        perceive_inorm_kernel<<<B_ * NF_, 256, 0, s0>>>(p_out, p_P);
        if (c == 0) cudaStreamWaitEvent(s0, ev[1], 0);
        if (c >= 2) cudaStreamWaitEvent(s0, ev[6 + (c & 1)], 0);
        dyna_fused_tc<<<dim3(HW_ / 128, B_), 256, SM_TOT * 4, s0>>>(
            p_dynp + (size_t)c * B_ * PDYN_, p_P, pe, p_out, catc);
        cudaEventRecord(ev[2 + c], s0);   // dyna(c) done

        // s1: otl chain for iter c (reads catc; writes other buffer's lat), split-K 32
        cudaStreamWaitEvent(s1, ev[2 + c], 0);
        const float* w1c = otl_w1 + (size_t)c * CAT_ * CAT_;
        const float* b1c = otl_b1 + (size_t)c * CAT_;
        const float* w2c = otl_w2 + (size_t)c * CAT_ * LAT_;
        const float* b2c = otl_b2 + (size_t)c * LAT_;
        const float* wsc = otl_ws + (size_t)c * CAT_ * LAT_;
        const float* bsc = otl_bs + (size_t)c * LAT_;
        latk_pair<<<dim3(10, 32), 256, 16 * (CAT_ / 32) * 4, s1>>>(
            catc, CAT_, w1c, CAT_, p_pA, wsc, LAT_, p_pB, CAT_);
        if (c < 2) {
            zero_freq_kernel<<<(B_ * (CAT_ - LAT_) + 255) / 256, 256, 0, s1>>>(catc);
            cudaEventRecord(ev[6 + (c & 1)], s1);
        }
        latk_mid<<<dim3(2, 32), 256, 16 * (CAT_ / 32) * 4, s1>>>(
            p_pA, b1c, w2c, p_pC, CAT_, 32);
        reduce_final<<<32, 256, 0, s1>>>(p_pC, p_pB, b2c, bsc, cat[(c + 1) & 1], CAT_, 32);
    }

    // ---- s1: final projection (lat lives in cat[0] after reduce_final(3)) ----
    latk_gemm<0><<<dim3(2, 32), 256, 16 * (LAT_ / 32) * 4, s1>>>(
        p_cat0, CAT_, ltl_w, nullptr, p_pA, LAT_, LAT_);
    reduce_plain<<<32, 256, 0, s1>>>(p_pA, ltl_b, (float*)d_out, LAT_, 32);

    // ---- join ----
    cudaEventRecord(ev[8], s1);
    cudaStreamWaitEvent(s0, ev[8], 0);
}